// round 6
// baseline (speedup 1.0000x reference)
#include <cuda_runtime.h>
#include <math.h>

#define BB 64
#define NCAPC 64
#define LVC 197
#define NSP 196
#define LTC 32
#define CCH 512
#define NKEEP 98
#define KEEPEDC 49
#define HIDC 102
#define LN_EPSF 1e-5f

// ---------------- scratch (__device__ globals; allocation-free) ----------------
__device__ float g_inv_img[BB * LVC];                    // 1/max(||row||,1e-12) per image row
__device__ float g_attn_x[BB * NSP];
__device__ float g_attn_y[(size_t)NCAPC * BB * NSP];     // [i][b][j]
__device__ float g_W0[(size_t)BB * NSP * KEEPEDC];       // (gelu(ln(x)@w1+b1))@w2+b2 per image token
__device__ float g_CAT[(size_t)NCAPC * 96 * CCH];        // per caption: [cap_norm(32); i2t(32); t2i(32)] x 512
__device__ float g_gloT[CCH * NCAPC];                    // cap_glo transposed [c][i]

__device__ __forceinline__ float warpReduceSum(float v) {
    #pragma unroll
    for (int o = 16; o > 0; o >>= 1) v += __shfl_xor_sync(0xffffffffu, v, o);
    return v;
}
__device__ __forceinline__ float warpReduceMax(float v) {
    #pragma unroll
    for (int o = 16; o > 0; o >>= 1) v = fmaxf(v, __shfl_xor_sync(0xffffffffu, v, o));
    return v;
}

// ---------------- K1: inverse norms for all image rows ----------------
__global__ void k_inv(const float* __restrict__ img) {
    int r = blockIdx.x;
    const float* x = img + (size_t)r * CCH;
    int tid = threadIdx.x;
    float ss = 0.f;
    for (int c = tid; c < CCH; c += 128) { float v = x[c]; ss += v * v; }
    __shared__ float red[4];
    ss = warpReduceSum(ss);
    if ((tid & 31) == 0) red[tid >> 5] = ss;
    __syncthreads();
    if (tid == 0) {
        float t = red[0] + red[1] + red[2] + red[3];
        g_inv_img[r] = 1.f / fmaxf(sqrtf(t), 1e-12f);
    }
}

// ---------------- K2: attn_x[b,j] = <img_norm[b,0], img_norm[b,1+j]> ----------------
__global__ void k_attnx(const float* __restrict__ img) {
    int r = blockIdx.x; int b = r / NSP; int j = r - b * NSP;
    const float* x0 = img + (size_t)b * LVC * CCH;
    const float* xj = x0 + (size_t)(1 + j) * CCH;
    int tid = threadIdx.x;
    float d = 0.f;
    for (int c = tid; c < CCH; c += 128) d += x0[c] * xj[c];
    __shared__ float red[4];
    d = warpReduceSum(d);
    if ((tid & 31) == 0) red[tid >> 5] = d;
    __syncthreads();
    if (tid == 0) {
        float t = red[0] + red[1] + red[2] + red[3];
        g_attn_x[r] = t * g_inv_img[b * LVC] * g_inv_img[b * LVC + 1 + j];
    }
}

// ---------------- K3: cap_norm rows -> CAT[i][0..31]; cap_glo transposed ----------------
__global__ void k_cap(const float* __restrict__ cap) {
    int r = blockIdx.x; int i = r / LTC; int t = r - i * LTC;
    const float* x = cap + (size_t)r * CCH;
    int tid = threadIdx.x;
    float ss = 0.f;
    for (int c = tid; c < CCH; c += 128) { float v = x[c]; ss += v * v; }
    __shared__ float red[4]; __shared__ float s_inv;
    ss = warpReduceSum(ss);
    if ((tid & 31) == 0) red[tid >> 5] = ss;
    __syncthreads();
    if (tid == 0) s_inv = 1.f / fmaxf(sqrtf(red[0] + red[1] + red[2] + red[3]), 1e-12f);
    __syncthreads();
    float inv = s_inv;
    float* dst = g_CAT + ((size_t)i * 96 + t) * CCH;
    for (int c = tid; c < CCH; c += 128) {
        float v = x[c] * inv;
        dst[c] = v;
        if (t == 0) g_gloT[c * NCAPC + i] = v;   // cap_glo == normalize(cap[i,0])
    }
}

// ---------------- K4: CAT[i][32..63] = cap_norm@wi2t+bi2t ; [64..95] = @wt2i+bt2i ----------------
__global__ __launch_bounds__(256) void k_capW(
    const float* __restrict__ wi2t, const float* __restrict__ bi2t,
    const float* __restrict__ wt2i, const float* __restrict__ bt2i) {
    extern __shared__ float s_x[];   // 32*512 floats
    int i = blockIdx.x >> 1; int which = blockIdx.x & 1;
    int tid = threadIdx.x;
    const float* src = g_CAT + (size_t)i * 96 * CCH;   // rows 0..31 contiguous
    for (int idx = tid; idx < LTC * CCH; idx += 256) s_x[idx] = src[idx];
    __syncthreads();
    const float* W    = which ? wt2i : wi2t;
    const float* bias = which ? bt2i : bi2t;
    int c0 = tid * 2;
    float acc0[LTC]; float acc1[LTC];
    #pragma unroll
    for (int t = 0; t < LTC; t++) { acc0[t] = 0.f; acc1[t] = 0.f; }
    for (int ci = 0; ci < CCH; ci++) {
        float w0 = W[(size_t)ci * CCH + c0];
        float w1v = W[(size_t)ci * CCH + c0 + 1];
        #pragma unroll
        for (int t = 0; t < LTC; t++) {
            float xv = s_x[t * CCH + ci];
            acc0[t] += w0 * xv; acc1[t] += w1v * xv;
        }
    }
    float bb0 = bias[c0], bb1 = bias[c0 + 1];
    float* dst = g_CAT + ((size_t)i * 96 + 32 + which * 32) * CCH;
    #pragma unroll
    for (int t = 0; t < LTC; t++) {
        dst[(size_t)t * CCH + c0]     = acc0[t] + bb0;
        dst[(size_t)t * CCH + c0 + 1] = acc1[t] + bb1;
    }
}

// ---------------- K5: per image token: W0 = gelu(ln(x)@w1+b1)@w2+b2 ----------------
__global__ void k_W0(const float* __restrict__ img,
                     const float* __restrict__ gamma, const float* __restrict__ beta,
                     const float* __restrict__ w1, const float* __restrict__ b1,
                     const float* __restrict__ w2, const float* __restrict__ b2) {
    int r = blockIdx.x; int b = r / NSP; int j = r - b * NSP;
    const float* x = img + ((size_t)b * LVC + 1 + j) * CCH;
    int tid = threadIdx.x;
    __shared__ float s_y[CCH];
    __shared__ float s_h[HIDC];
    __shared__ float red[4], red2[4];
    __shared__ float s_mean, s_rstd;
    float s = 0.f, ss = 0.f;
    for (int c = tid; c < CCH; c += 128) { float v = x[c]; s += v; ss += v * v; }
    s = warpReduceSum(s); ss = warpReduceSum(ss);
    if ((tid & 31) == 0) { red[tid >> 5] = s; red2[tid >> 5] = ss; }
    __syncthreads();
    if (tid == 0) {
        float S = red[0] + red[1] + red[2] + red[3];
        float SS = red2[0] + red2[1] + red2[2] + red2[3];
        float mean = S * (1.f / CCH);
        float var = SS * (1.f / CCH) - mean * mean;
        s_mean = mean; s_rstd = 1.f / sqrtf(var + LN_EPSF);
    }
    __syncthreads();
    float mean = s_mean, rstd = s_rstd;
    for (int c = tid; c < CCH; c += 128)
        s_y[c] = (x[c] - mean) * rstd * gamma[c] + beta[c];
    __syncthreads();
    if (tid < HIDC) {
        float acc = b1[tid];
        for (int c = 0; c < CCH; c++) acc += s_y[c] * w1[(size_t)c * HIDC + tid];
        s_h[tid] = 0.5f * acc * (1.f + erff(acc * 0.70710678118654752f));   // exact gelu
    }
    __syncthreads();
    if (tid < KEEPEDC) {
        float acc = b2[tid];
        for (int h = 0; h < HIDC; h++) acc += s_h[h] * w2[h * KEEPEDC + tid];
        g_W0[(size_t)r * KEEPEDC + tid] = acc;
    }
}

// ---------------- K6: attn_y[i][b][j] = <img_sp_norm[b,j], cap_glo[i]> ----------------
__global__ void k_attn_y(const float* __restrict__ img) {
    int r = blockIdx.x; int b = r / NSP; int j = r - b * NSP;
    const float* x = img + ((size_t)b * LVC + 1 + j) * CCH;
    int tid = threadIdx.x;  // 64 threads, one caption each
    __shared__ float s_x[CCH];
    for (int c = tid; c < CCH; c += 64) s_x[c] = x[c];
    __syncthreads();
    float acc = 0.f;
    for (int c = 0; c < CCH; c++) acc += s_x[c] * g_gloT[c * NCAPC + tid];
    float val = acc * g_inv_img[b * LVC + 1 + j];
    g_attn_y[((size_t)tid * BB + b) * NSP + j] = val;
}

// ---------------- K7: per-pair fused kernel ----------------
#define ST_ROW 520
#define OFF_ST 0
#define SZ_ST (51 * ST_ROW)                 // 26520
#define OFF_U SZ_ST
#define OFF_A OFF_U                          // 49*98 = 4802 (dead before E)
#define OFF_WNON (OFF_U + KEEPEDC * NKEEP)   // 98
#define OFF_E OFF_U                          // 96*132 = 12672
#define OFF_G (OFF_U + 96 * 132)             // 4896
#define OFF_CM (OFF_G + 96 * 51)
#define OFF_CZ (OFF_CM + 51)
#define OFF_RM (OFF_CZ + 51)
#define OFF_RZ (OFF_RM + 32)
#define SZ_U (96 * 132 + 96 * 51 + 51 + 51 + 32 + 32)   // 17734
#define OFF_SCORE (OFF_U + SZ_U)
#define OFF_ORDER (OFF_SCORE + 196)
#define OFF_RED (OFF_ORDER + 196)
#define OFF_SCAL (OFF_RED + 8)
#define SMEM_FLOATS (OFF_SCAL + 4)           // 44658 floats = 178632 B

__global__ __launch_bounds__(256, 1) void k_pair(
    const float* __restrict__ img,
    const float* __restrict__ aggr_scale_p,
    const float* __restrict__ temp_p,
    float* __restrict__ out) {
    extern __shared__ float sm[];
    float* s_st    = sm + OFF_ST;
    float* s_A     = sm + OFF_A;
    float* s_wnon  = sm + OFF_WNON;
    float* s_E     = sm + OFF_E;
    float* s_G     = sm + OFF_G;
    float* s_cm    = sm + OFF_CM;
    float* s_cz    = sm + OFF_CZ;
    float* s_rm    = sm + OFF_RM;
    float* s_rz    = sm + OFF_RZ;
    float* s_score = sm + OFF_SCORE;
    int*   s_order = (int*)(sm + OFF_ORDER);
    float* s_red   = sm + OFF_RED;
    float* s_scal  = sm + OFF_SCAL;

    int pair = blockIdx.x;
    int i = pair & (NCAPC - 1);
    int b = pair >> 6;
    int tid = threadIdx.x;
    int lane = tid & 31, wid = tid >> 5;

    // ---- 1. scores ----
    {
        const float* ay = g_attn_y + ((size_t)i * BB + b) * NSP;
        const float* ax = g_attn_x + (size_t)b * NSP;
        for (int j = tid; j < NSP; j += 256) s_score[j] = ax[j] + ay[j];
    }
    __syncthreads();

    // ---- 2. deterministic rank (== stable argsort(-score) position) ----
    if (tid < NSP) {
        float sj = s_score[tid];
        int rank = 0;
        for (int j2 = 0; j2 < NSP; j2++) {
            float s2 = s_score[j2];
            rank += (s2 > sj) || (s2 == sj && j2 < tid);
        }
        s_order[rank] = tid;
    }
    __syncthreads();

    // ---- 3a. softmax weights over nonkeep scores ----
    {
        float m = -INFINITY;
        for (int jj = NKEEP + tid; jj < NSP; jj += 256) m = fmaxf(m, s_score[s_order[jj]]);
        m = warpReduceMax(m);
        if (lane == 0) s_red[wid] = m;
    }
    __syncthreads();
    if (tid == 0) {
        float mm = -INFINITY;
        for (int w = 0; w < 8; w++) mm = fmaxf(mm, s_red[w]);
        s_scal[0] = mm;
    }
    __syncthreads();
    {
        float mnon = s_scal[0];
        float z = 0.f;
        for (int jj = NKEEP + tid; jj < NSP; jj += 256) {
            float e = expf(s_score[s_order[jj]] - mnon);
            s_wnon[jj - NKEEP] = e; z += e;
        }
        z = warpReduceSum(z);
        if (lane == 0) s_red[wid] = z;
    }
    __syncthreads();
    if (tid == 0) {
        float zz = 0.f;
        for (int w = 0; w < 8; w++) zz += s_red[w];
        s_scal[1] = 1.f / zz;
    }
    // ---- 3b. gather A = aggr_scale * W0[b, keep, :] (transposed to [k][jj]) ----
    {
        float ascale = aggr_scale_p[0];
        for (int idx = tid; idx < KEEPEDC * NKEEP; idx += 256) {
            int jj = idx / KEEPEDC; int k = idx - jj * KEEPEDC;
            int j = s_order[jj];
            s_A[k * NKEEP + jj] = g_W0[((size_t)b * NSP + j) * KEEPEDC + k] * ascale;
        }
    }
    __syncthreads();
    // ---- 3c. per-k softmax over 98 keep entries ----
    for (int k = wid; k < KEEPEDC; k += 8) {
        float km = -INFINITY;
        for (int jj = lane; jj < NKEEP; jj += 32) km = fmaxf(km, s_A[k * NKEEP + jj]);
        km = warpReduceMax(km);
        float kz = 0.f;
        for (int jj = lane; jj < NKEEP; jj += 32) {
            float e = expf(s_A[k * NKEEP + jj] - km);
            s_A[k * NKEEP + jj] = e; kz += e;
        }
        kz = warpReduceSum(kz);
        float inv = 1.f / kz;
        for (int jj = lane; jj < NKEEP; jj += 32) s_A[k * NKEEP + jj] *= inv;
    }
    __syncthreads();

    // ---- 4. aggr (49 rows) + extra + cls -> unnormalized sel_tok in smem ----
    {
        const float* spbase = img + ((size_t)b * LVC + 1) * CCH;
        float2 acc[KEEPEDC];
        #pragma unroll
        for (int k = 0; k < KEEPEDC; k++) { acc[k].x = 0.f; acc[k].y = 0.f; }
        for (int jj = 0; jj < NKEEP; jj++) {
            int j = s_order[jj];
            float2 x = ((const float2*)(spbase + (size_t)j * CCH))[tid];
            #pragma unroll
            for (int k = 0; k < KEEPEDC; k++) {
                float a = s_A[k * NKEEP + jj];
                acc[k].x += a * x.x; acc[k].y += a * x.y;
            }
        }
        float2 wacc; wacc.x = 0.f; wacc.y = 0.f;
        for (int jj = NKEEP; jj < NSP; jj++) {
            int j = s_order[jj];
            float2 x = ((const float2*)(spbase + (size_t)j * CCH))[tid];
            float wv = s_wnon[jj - NKEEP];
            wacc.x += wv * x.x; wacc.y += wv * x.y;
        }
        float invz = s_scal[1];
        float2 cls = ((const float2*)(img + (size_t)b * LVC * CCH))[tid];
        int c0 = tid * 2;
        s_st[0 * ST_ROW + c0] = cls.x; s_st[0 * ST_ROW + c0 + 1] = cls.y;
        #pragma unroll
        for (int k = 0; k < KEEPEDC; k++) {
            s_st[(1 + k) * ST_ROW + c0]     = acc[k].x;
            s_st[(1 + k) * ST_ROW + c0 + 1] = acc[k].y;
        }
        s_st[50 * ST_ROW + c0]     = wacc.x * invz;
        s_st[50 * ST_ROW + c0 + 1] = wacc.y * invz;
    }
    __syncthreads();

    // ---- 5. L2-normalize the 51 sel_tok rows ----
    for (int row = wid; row < 51; row += 8) {
        float ssq = 0.f;
        for (int c = lane; c < CCH; c += 32) { float v = s_st[row * ST_ROW + c]; ssq += v * v; }
        ssq = warpReduceSum(ssq);
        float inv = 1.f / fmaxf(sqrtf(ssq), 1e-12f);
        for (int c = lane; c < CCH; c += 32) s_st[row * ST_ROW + c] *= inv;
    }
    __syncthreads();

    // ---- 6. G[t][l] = sum_c CAT_i[t][c] * sel_tok[l][c]  (96x51, K=512 in 4 chunks) ----
    {
        const float* E = g_CAT + (size_t)i * 96 * CCH;
        float acc3[8][3];
        #pragma unroll
        for (int a = 0; a < 8; a++)
            #pragma unroll
            for (int l = 0; l < 3; l++) acc3[a][l] = 0.f;
        int lgrp = tid % 17, tq = tid / 17;
        bool active = (tid < 204);
        int l0 = lgrp * 3, t0 = tq * 8;
        for (int ch = 0; ch < 4; ch++) {
            int c0 = ch * 128;
            for (int idx = tid * 4; idx < 96 * 128; idx += 1024) {
                int t = idx >> 7; int cc = idx & 127;
                float4 v = *(const float4*)(E + (size_t)t * CCH + c0 + cc);
                *(float4*)(s_E + t * 132 + cc) = v;
            }
            __syncthreads();
            if (active) {
                for (int cc = 0; cc < 128; cc += 4) {
                    float4 st0 = *(const float4*)(s_st + (l0 + 0) * ST_ROW + c0 + cc);
                    float4 st1 = *(const float4*)(s_st + (l0 + 1) * ST_ROW + c0 + cc);
                    float4 st2 = *(const float4*)(s_st + (l0 + 2) * ST_ROW + c0 + cc);
                    #pragma unroll
                    for (int a = 0; a < 8; a++) {
                        float4 e = *(const float4*)(s_E + (t0 + a) * 132 + cc);
                        acc3[a][0] += e.x * st0.x + e.y * st0.y + e.z * st0.z + e.w * st0.w;
                        acc3[a][1] += e.x * st1.x + e.y * st1.y + e.z * st1.z + e.w * st1.w;
                        acc3[a][2] += e.x * st2.x + e.y * st2.y + e.z * st2.z + e.w * st2.w;
                    }
                }
            }
            __syncthreads();
        }
        if (active) {
            #pragma unroll
            for (int a = 0; a < 8; a++)
                #pragma unroll
                for (int l = 0; l < 3; l++)
                    s_G[(t0 + a) * 51 + l0 + l] = acc3[a][l];
        }
    }
    __syncthreads();

    // ---- 7. softmaxes + final reduction ----
    float invtemp = 1.f / temp_p[0];
    if (tid < 51) {                               // column stats for a_i2t (softmax over t)
        int l = tid;
        float cm = -INFINITY;
        for (int t = 0; t < 32; t++) cm = fmaxf(cm, s_G[(32 + t) * 51 + l] * invtemp);
        float cz = 0.f;
        for (int t = 0; t < 32; t++) cz += expf(s_G[(32 + t) * 51 + l] * invtemp - cm);
        s_cm[l] = cm; s_cz[l] = cz;
    } else if (tid >= 64 && tid < 96) {           // row stats for a_t2i (softmax over l)
        int t = tid - 64;
        float rm = -INFINITY;
        for (int l = 0; l < 51; l++) rm = fmaxf(rm, s_G[(64 + t) * 51 + l] * invtemp);
        float rz = 0.f;
        for (int l = 0; l < 51; l++) rz += expf(s_G[(64 + t) * 51 + l] * invtemp - rm);
        s_rm[t] = rm; s_rz[t] = rz;
    }
    __syncthreads();
    float part = 0.f;
    for (int idx = tid; idx < 32 * 51; idx += 256) {
        int t = idx / 51; int l = idx - t * 51;
        float g = s_G[t * 51 + l];
        float c2i = (g >= 0.f) ? g : 0.1f * g;               // leaky_relu 0.1
        float li = s_G[(32 + t) * 51 + l] * invtemp;
        float lt = s_G[(64 + t) * 51 + l] * invtemp;
        float ai = expf(li - s_cm[l]) / s_cz[l];
        float at = expf(lt - s_rm[t]) / s_rz[t];
        part += c2i * (ai * (1.f / 51.f) + at * (1.f / 32.f));
    }
    part = warpReduceSum(part);
    if (lane == 0) s_red[wid] = part;
    __syncthreads();
    if (tid == 0) {
        float s = 0.f;
        for (int w = 0; w < 8; w++) s += s_red[w];
        out[b * NCAPC + i] = s;                   // sims.T[b, i]
    }
}

// ---------------- launch ----------------
extern "C" void kernel_launch(void* const* d_in, const int* in_sizes, int n_in,
                              void* d_out, int out_size) {
    const float* img    = (const float*)d_in[0];
    const float* cap    = (const float*)d_in[1];
    // d_in[2] cap_lens: always LT, unused
    const float* gamma  = (const float*)d_in[3];
    const float* beta   = (const float*)d_in[4];
    const float* w1     = (const float*)d_in[5];
    const float* b1     = (const float*)d_in[6];
    const float* w2     = (const float*)d_in[7];
    const float* b2     = (const float*)d_in[8];
    const float* ascale = (const float*)d_in[9];
    const float* wi2t   = (const float*)d_in[10];
    const float* bi2t   = (const float*)d_in[11];
    const float* wt2i   = (const float*)d_in[12];
    const float* bt2i   = (const float*)d_in[13];
    const float* temp   = (const float*)d_in[14];
    float* out = (float*)d_out;

    cudaFuncSetAttribute(k_capW, cudaFuncAttributeMaxDynamicSharedMemorySize, LTC * CCH * 4);
    cudaFuncSetAttribute(k_pair, cudaFuncAttributeMaxDynamicSharedMemorySize, SMEM_FLOATS * 4);

    k_inv<<<BB * LVC, 128>>>(img);
    k_cap<<<NCAPC * LTC, 128>>>(cap);
    k_attnx<<<BB * NSP, 128>>>(img);
    k_capW<<<NCAPC * 2, 256, LTC * CCH * 4>>>(wi2t, bi2t, wt2i, bt2i);
    k_W0<<<BB * NSP, 128>>>(img, gamma, beta, w1, b1, w2, b2);
    k_attn_y<<<BB * NSP, 64>>>(img);
    k_pair<<<NCAPC * BB, 256, SMEM_FLOATS * 4>>>(img, ascale, temp, out);
}

// round 7
// speedup vs baseline: 1.0002x; 1.0002x over previous
#include <cuda_runtime.h>
#include <math.h>

#define BB 64
#define NCAPC 64
#define LVC 197
#define NSP 196
#define LTC 32
#define CCH 512
#define NKEEP 98
#define KEEPEDC 49
#define HIDC 102
#define LN_EPSF 1e-5f

// ---------------- scratch (__device__ globals; allocation-free) ----------------
__device__ float g_inv_img[BB * LVC];                    // 1/max(||row||,1e-12) per image row
__device__ float g_attn_x[BB * NSP];
__device__ float g_attn_y[(size_t)NCAPC * BB * NSP];     // [i][b][j]
__device__ float g_W0[(size_t)BB * NSP * KEEPEDC];       // (gelu(ln(x)@w1+b1))@w2+b2 per image token
__device__ float g_CAT[(size_t)NCAPC * 96 * CCH];        // per caption: [cap_norm(32); i2t(32); t2i(32)] x 512
__device__ float g_gloT[CCH * NCAPC];                    // cap_glo transposed [c][i]

__device__ __forceinline__ float warpReduceSum(float v) {
    #pragma unroll
    for (int o = 16; o > 0; o >>= 1) v += __shfl_xor_sync(0xffffffffu, v, o);
    return v;
}
__device__ __forceinline__ float warpReduceMax(float v) {
    #pragma unroll
    for (int o = 16; o > 0; o >>= 1) v = fmaxf(v, __shfl_xor_sync(0xffffffffu, v, o));
    return v;
}

// ---------------- K1: inverse norms for all image rows ----------------
__global__ void k_inv(const float* __restrict__ img) {
    int r = blockIdx.x;
    const float* x = img + (size_t)r * CCH;
    int tid = threadIdx.x;
    float ss = 0.f;
    for (int c = tid; c < CCH; c += 128) { float v = x[c]; ss += v * v; }
    __shared__ float red[4];
    ss = warpReduceSum(ss);
    if ((tid & 31) == 0) red[tid >> 5] = ss;
    __syncthreads();
    if (tid == 0) {
        float t = red[0] + red[1] + red[2] + red[3];
        g_inv_img[r] = 1.f / fmaxf(sqrtf(t), 1e-12f);
    }
}

// ---------------- K2: attn_x[b,j] = <img_norm[b,0], img_norm[b,1+j]> ----------------
__global__ void k_attnx(const float* __restrict__ img) {
    int r = blockIdx.x; int b = r / NSP; int j = r - b * NSP;
    const float* x0 = img + (size_t)b * LVC * CCH;
    const float* xj = x0 + (size_t)(1 + j) * CCH;
    int tid = threadIdx.x;
    float d = 0.f;
    for (int c = tid; c < CCH; c += 128) d += x0[c] * xj[c];
    __shared__ float red[4];
    d = warpReduceSum(d);
    if ((tid & 31) == 0) red[tid >> 5] = d;
    __syncthreads();
    if (tid == 0) {
        float t = red[0] + red[1] + red[2] + red[3];
        g_attn_x[r] = t * g_inv_img[b * LVC] * g_inv_img[b * LVC + 1 + j];
    }
}

// ---------------- K3: cap_norm rows -> CAT[i][0..31]; cap_glo transposed ----------------
__global__ void k_cap(const float* __restrict__ cap) {
    int r = blockIdx.x; int i = r / LTC; int t = r - i * LTC;
    const float* x = cap + (size_t)r * CCH;
    int tid = threadIdx.x;
    float ss = 0.f;
    for (int c = tid; c < CCH; c += 128) { float v = x[c]; ss += v * v; }
    __shared__ float red[4]; __shared__ float s_inv;
    ss = warpReduceSum(ss);
    if ((tid & 31) == 0) red[tid >> 5] = ss;
    __syncthreads();
    if (tid == 0) s_inv = 1.f / fmaxf(sqrtf(red[0] + red[1] + red[2] + red[3]), 1e-12f);
    __syncthreads();
    float inv = s_inv;
    float* dst = g_CAT + ((size_t)i * 96 + t) * CCH;
    for (int c = tid; c < CCH; c += 128) {
        float v = x[c] * inv;
        dst[c] = v;
        if (t == 0) g_gloT[c * NCAPC + i] = v;   // cap_glo == normalize(cap[i,0])
    }
}

// ---------------- K4: CAT[i][32..63] = cap_norm@wi2t+bi2t ; [64..95] = @wt2i+bt2i ----------------
__global__ __launch_bounds__(256) void k_capW(
    const float* __restrict__ wi2t, const float* __restrict__ bi2t,
    const float* __restrict__ wt2i, const float* __restrict__ bt2i) {
    extern __shared__ float s_x[];   // 32*512 floats
    int i = blockIdx.x >> 1; int which = blockIdx.x & 1;
    int tid = threadIdx.x;
    const float* src = g_CAT + (size_t)i * 96 * CCH;   // rows 0..31 contiguous
    for (int idx = tid; idx < LTC * CCH; idx += 256) s_x[idx] = src[idx];
    __syncthreads();
    const float* W    = which ? wt2i : wi2t;
    const float* bias = which ? bt2i : bi2t;
    int c0 = tid * 2;
    float acc0[LTC]; float acc1[LTC];
    #pragma unroll
    for (int t = 0; t < LTC; t++) { acc0[t] = 0.f; acc1[t] = 0.f; }
    for (int ci = 0; ci < CCH; ci++) {
        float w0 = W[(size_t)ci * CCH + c0];
        float w1v = W[(size_t)ci * CCH + c0 + 1];
        #pragma unroll
        for (int t = 0; t < LTC; t++) {
            float xv = s_x[t * CCH + ci];
            acc0[t] += w0 * xv; acc1[t] += w1v * xv;
        }
    }
    float bb0 = bias[c0], bb1 = bias[c0 + 1];
    float* dst = g_CAT + ((size_t)i * 96 + 32 + which * 32) * CCH;
    #pragma unroll
    for (int t = 0; t < LTC; t++) {
        dst[(size_t)t * CCH + c0]     = acc0[t] + bb0;
        dst[(size_t)t * CCH + c0 + 1] = acc1[t] + bb1;
    }
}

// ---------------- K5: per image token: W0 = gelu(ln(x)@w1+b1)@w2+b2 ----------------
__global__ void k_W0(const float* __restrict__ img,
                     const float* __restrict__ gamma, const float* __restrict__ beta,
                     const float* __restrict__ w1, const float* __restrict__ b1,
                     const float* __restrict__ w2, const float* __restrict__ b2) {
    int r = blockIdx.x; int b = r / NSP; int j = r - b * NSP;
    const float* x = img + ((size_t)b * LVC + 1 + j) * CCH;
    int tid = threadIdx.x;
    __shared__ float s_y[CCH];
    __shared__ float s_h[HIDC];
    __shared__ float red[4], red2[4];
    __shared__ float s_mean, s_rstd;
    float s = 0.f, ss = 0.f;
    for (int c = tid; c < CCH; c += 128) { float v = x[c]; s += v; ss += v * v; }
    s = warpReduceSum(s); ss = warpReduceSum(ss);
    if ((tid & 31) == 0) { red[tid >> 5] = s; red2[tid >> 5] = ss; }
    __syncthreads();
    if (tid == 0) {
        float S = red[0] + red[1] + red[2] + red[3];
        float SS = red2[0] + red2[1] + red2[2] + red2[3];
        float mean = S * (1.f / CCH);
        float var = SS * (1.f / CCH) - mean * mean;
        s_mean = mean; s_rstd = 1.f / sqrtf(var + LN_EPSF);
    }
    __syncthreads();
    float mean = s_mean, rstd = s_rstd;
    for (int c = tid; c < CCH; c += 128)
        s_y[c] = (x[c] - mean) * rstd * gamma[c] + beta[c];
    __syncthreads();
    if (tid < HIDC) {
        float acc = b1[tid];
        for (int c = 0; c < CCH; c++) acc += s_y[c] * w1[(size_t)c * HIDC + tid];
        s_h[tid] = 0.5f * acc * (1.f + erff(acc * 0.70710678118654752f));   // exact gelu
    }
    __syncthreads();
    if (tid < KEEPEDC) {
        float acc = b2[tid];
        for (int h = 0; h < HIDC; h++) acc += s_h[h] * w2[h * KEEPEDC + tid];
        g_W0[(size_t)r * KEEPEDC + tid] = acc;
    }
}

// ---------------- K6: attn_y[i][b][j] = <img_sp_norm[b,j], cap_glo[i]> ----------------
__global__ void k_attn_y(const float* __restrict__ img) {
    int r = blockIdx.x; int b = r / NSP; int j = r - b * NSP;
    const float* x = img + ((size_t)b * LVC + 1 + j) * CCH;
    int tid = threadIdx.x;  // 64 threads, one caption each
    __shared__ float s_x[CCH];
    for (int c = tid; c < CCH; c += 64) s_x[c] = x[c];
    __syncthreads();
    float acc = 0.f;
    for (int c = 0; c < CCH; c++) acc += s_x[c] * g_gloT[c * NCAPC + tid];
    float val = acc * g_inv_img[b * LVC + 1 + j];
    g_attn_y[((size_t)tid * BB + b) * NSP + j] = val;
}

// ---------------- K7: per-pair fused kernel ----------------
#define ST_ROW 520
#define OFF_ST 0
#define SZ_ST (51 * ST_ROW)                 // 26520
#define OFF_U SZ_ST
#define OFF_A OFF_U                          // 49*98 = 4802 (dead before E)
#define OFF_WNON (OFF_U + KEEPEDC * NKEEP)   // 98
#define OFF_E OFF_U                          // 96*132 = 12672
#define OFF_G (OFF_U + 96 * 132)             // 4896
#define OFF_CM (OFF_G + 96 * 51)
#define OFF_CZ (OFF_CM + 51)
#define OFF_RM (OFF_CZ + 51)
#define OFF_RZ (OFF_RM + 32)
#define SZ_U (96 * 132 + 96 * 51 + 51 + 51 + 32 + 32)   // 17734
#define OFF_SCORE (OFF_U + SZ_U)
#define OFF_ORDER (OFF_SCORE + 196)
#define OFF_RED (OFF_ORDER + 196)
#define OFF_SCAL (OFF_RED + 8)
#define SMEM_FLOATS (OFF_SCAL + 4)           // 44658 floats = 178632 B

__global__ __launch_bounds__(256, 1) void k_pair(
    const float* __restrict__ img,
    const float* __restrict__ aggr_scale_p,
    const float* __restrict__ temp_p,
    float* __restrict__ out) {
    extern __shared__ float sm[];
    float* s_st    = sm + OFF_ST;
    float* s_A     = sm + OFF_A;
    float* s_wnon  = sm + OFF_WNON;
    float* s_E     = sm + OFF_E;
    float* s_G     = sm + OFF_G;
    float* s_cm    = sm + OFF_CM;
    float* s_cz    = sm + OFF_CZ;
    float* s_rm    = sm + OFF_RM;
    float* s_rz    = sm + OFF_RZ;
    float* s_score = sm + OFF_SCORE;
    int*   s_order = (int*)(sm + OFF_ORDER);
    float* s_red   = sm + OFF_RED;
    float* s_scal  = sm + OFF_SCAL;

    int pair = blockIdx.x;
    int i = pair & (NCAPC - 1);
    int b = pair >> 6;
    int tid = threadIdx.x;
    int lane = tid & 31, wid = tid >> 5;

    // ---- 1. scores ----
    {
        const float* ay = g_attn_y + ((size_t)i * BB + b) * NSP;
        const float* ax = g_attn_x + (size_t)b * NSP;
        for (int j = tid; j < NSP; j += 256) s_score[j] = ax[j] + ay[j];
    }
    __syncthreads();

    // ---- 2. deterministic rank (== stable argsort(-score) position) ----
    if (tid < NSP) {
        float sj = s_score[tid];
        int rank = 0;
        for (int j2 = 0; j2 < NSP; j2++) {
            float s2 = s_score[j2];
            rank += (s2 > sj) || (s2 == sj && j2 < tid);
        }
        s_order[rank] = tid;
    }
    __syncthreads();

    // ---- 3a. softmax weights over nonkeep scores ----
    {
        float m = -INFINITY;
        for (int jj = NKEEP + tid; jj < NSP; jj += 256) m = fmaxf(m, s_score[s_order[jj]]);
        m = warpReduceMax(m);
        if (lane == 0) s_red[wid] = m;
    }
    __syncthreads();
    if (tid == 0) {
        float mm = -INFINITY;
        for (int w = 0; w < 8; w++) mm = fmaxf(mm, s_red[w]);
        s_scal[0] = mm;
    }
    __syncthreads();
    {
        float mnon = s_scal[0];
        float z = 0.f;
        for (int jj = NKEEP + tid; jj < NSP; jj += 256) {
            float e = expf(s_score[s_order[jj]] - mnon);
            s_wnon[jj - NKEEP] = e; z += e;
        }
        z = warpReduceSum(z);
        if (lane == 0) s_red[wid] = z;
    }
    __syncthreads();
    if (tid == 0) {
        float zz = 0.f;
        for (int w = 0; w < 8; w++) zz += s_red[w];
        s_scal[1] = 1.f / zz;
    }
    // ---- 3b. gather A = aggr_scale * W0[b, keep, :] (transposed to [k][jj]) ----
    {
        float ascale = aggr_scale_p[0];
        for (int idx = tid; idx < KEEPEDC * NKEEP; idx += 256) {
            int jj = idx / KEEPEDC; int k = idx - jj * KEEPEDC;
            int j = s_order[jj];
            s_A[k * NKEEP + jj] = g_W0[((size_t)b * NSP + j) * KEEPEDC + k] * ascale;
        }
    }
    __syncthreads();
    // ---- 3c. per-k softmax over 98 keep entries ----
    for (int k = wid; k < KEEPEDC; k += 8) {
        float km = -INFINITY;
        for (int jj = lane; jj < NKEEP; jj += 32) km = fmaxf(km, s_A[k * NKEEP + jj]);
        km = warpReduceMax(km);
        float kz = 0.f;
        for (int jj = lane; jj < NKEEP; jj += 32) {
            float e = expf(s_A[k * NKEEP + jj] - km);
            s_A[k * NKEEP + jj] = e; kz += e;
        }
        kz = warpReduceSum(kz);
        float inv = 1.f / kz;
        for (int jj = lane; jj < NKEEP; jj += 32) s_A[k * NKEEP + jj] *= inv;
    }
    __syncthreads();

    // ---- 4. aggr (49 rows) + extra + cls -> unnormalized sel_tok in smem ----
    {
        const float* spbase = img + ((size_t)b * LVC + 1) * CCH;
        float2 acc[KEEPEDC];
        #pragma unroll
        for (int k = 0; k < KEEPEDC; k++) { acc[k].x = 0.f; acc[k].y = 0.f; }
        for (int jj = 0; jj < NKEEP; jj++) {
            int j = s_order[jj];
            float2 x = ((const float2*)(spbase + (size_t)j * CCH))[tid];
            #pragma unroll
            for (int k = 0; k < KEEPEDC; k++) {
                float a = s_A[k * NKEEP + jj];
                acc[k].x += a * x.x; acc[k].y += a * x.y;
            }
        }
        float2 wacc; wacc.x = 0.f; wacc.y = 0.f;
        for (int jj = NKEEP; jj < NSP; jj++) {
            int j = s_order[jj];
            float2 x = ((const float2*)(spbase + (size_t)j * CCH))[tid];
            float wv = s_wnon[jj - NKEEP];
            wacc.x += wv * x.x; wacc.y += wv * x.y;
        }
        float invz = s_scal[1];
        float2 cls = ((const float2*)(img + (size_t)b * LVC * CCH))[tid];
        int c0 = tid * 2;
        s_st[0 * ST_ROW + c0] = cls.x; s_st[0 * ST_ROW + c0 + 1] = cls.y;
        #pragma unroll
        for (int k = 0; k < KEEPEDC; k++) {
            s_st[(1 + k) * ST_ROW + c0]     = acc[k].x;
            s_st[(1 + k) * ST_ROW + c0 + 1] = acc[k].y;
        }
        s_st[50 * ST_ROW + c0]     = wacc.x * invz;
        s_st[50 * ST_ROW + c0 + 1] = wacc.y * invz;
    }
    __syncthreads();

    // ---- 5. L2-normalize the 51 sel_tok rows ----
    for (int row = wid; row < 51; row += 8) {
        float ssq = 0.f;
        for (int c = lane; c < CCH; c += 32) { float v = s_st[row * ST_ROW + c]; ssq += v * v; }
        ssq = warpReduceSum(ssq);
        float inv = 1.f / fmaxf(sqrtf(ssq), 1e-12f);
        for (int c = lane; c < CCH; c += 32) s_st[row * ST_ROW + c] *= inv;
    }
    __syncthreads();

    // ---- 6. G[t][l] = sum_c CAT_i[t][c] * sel_tok[l][c]  (96x51, K=512 in 4 chunks) ----
    {
        const float* E = g_CAT + (size_t)i * 96 * CCH;
        float acc3[8][3];
        #pragma unroll
        for (int a = 0; a < 8; a++)
            #pragma unroll
            for (int l = 0; l < 3; l++) acc3[a][l] = 0.f;
        int lgrp = tid % 17, tq = tid / 17;
        bool active = (tid < 204);
        int l0 = lgrp * 3, t0 = tq * 8;
        for (int ch = 0; ch < 4; ch++) {
            int c0 = ch * 128;
            for (int idx = tid * 4; idx < 96 * 128; idx += 1024) {
                int t = idx >> 7; int cc = idx & 127;
                float4 v = *(const float4*)(E + (size_t)t * CCH + c0 + cc);
                *(float4*)(s_E + t * 132 + cc) = v;
            }
            __syncthreads();
            if (active) {
                for (int cc = 0; cc < 128; cc += 4) {
                    float4 st0 = *(const float4*)(s_st + (l0 + 0) * ST_ROW + c0 + cc);
                    float4 st1 = *(const float4*)(s_st + (l0 + 1) * ST_ROW + c0 + cc);
                    float4 st2 = *(const float4*)(s_st + (l0 + 2) * ST_ROW + c0 + cc);
                    #pragma unroll
                    for (int a = 0; a < 8; a++) {
                        float4 e = *(const float4*)(s_E + (t0 + a) * 132 + cc);
                        acc3[a][0] += e.x * st0.x + e.y * st0.y + e.z * st0.z + e.w * st0.w;
                        acc3[a][1] += e.x * st1.x + e.y * st1.y + e.z * st1.z + e.w * st1.w;
                        acc3[a][2] += e.x * st2.x + e.y * st2.y + e.z * st2.z + e.w * st2.w;
                    }
                }
            }
            __syncthreads();
        }
        if (active) {
            #pragma unroll
            for (int a = 0; a < 8; a++)
                #pragma unroll
                for (int l = 0; l < 3; l++)
                    s_G[(t0 + a) * 51 + l0 + l] = acc3[a][l];
        }
    }
    __syncthreads();

    // ---- 7. softmaxes + final reduction ----
    float invtemp = 1.f / temp_p[0];
    if (tid < 51) {                               // column stats for a_i2t (softmax over t)
        int l = tid;
        float cm = -INFINITY;
        for (int t = 0; t < 32; t++) cm = fmaxf(cm, s_G[(32 + t) * 51 + l] * invtemp);
        float cz = 0.f;
        for (int t = 0; t < 32; t++) cz += expf(s_G[(32 + t) * 51 + l] * invtemp - cm);
        s_cm[l] = cm; s_cz[l] = cz;
    } else if (tid >= 64 && tid < 96) {           // row stats for a_t2i (softmax over l)
        int t = tid - 64;
        float rm = -INFINITY;
        for (int l = 0; l < 51; l++) rm = fmaxf(rm, s_G[(64 + t) * 51 + l] * invtemp);
        float rz = 0.f;
        for (int l = 0; l < 51; l++) rz += expf(s_G[(64 + t) * 51 + l] * invtemp - rm);
        s_rm[t] = rm; s_rz[t] = rz;
    }
    __syncthreads();
    float part = 0.f;
    for (int idx = tid; idx < 32 * 51; idx += 256) {
        int t = idx / 51; int l = idx - t * 51;
        float g = s_G[t * 51 + l];
        float c2i = (g >= 0.f) ? g : 0.1f * g;               // leaky_relu 0.1
        float li = s_G[(32 + t) * 51 + l] * invtemp;
        float lt = s_G[(64 + t) * 51 + l] * invtemp;
        float ai = expf(li - s_cm[l]) / s_cz[l];
        float at = expf(lt - s_rm[t]) / s_rz[t];
        part += c2i * (ai * (1.f / 51.f) + at * (1.f / 32.f));
    }
    part = warpReduceSum(part);
    if (lane == 0) s_red[wid] = part;
    __syncthreads();
    if (tid == 0) {
        float s = 0.f;
        for (int w = 0; w < 8; w++) s += s_red[w];
        out[b * NCAPC + i] = s;                   // sims.T[b, i]
    }
}

// ---------------- launch ----------------
extern "C" void kernel_launch(void* const* d_in, const int* in_sizes, int n_in,
                              void* d_out, int out_size) {
    const float* img    = (const float*)d_in[0];
    const float* cap    = (const float*)d_in[1];
    // d_in[2] cap_lens: always LT, unused
    const float* gamma  = (const float*)d_in[3];
    const float* beta   = (const float*)d_in[4];
    const float* w1     = (const float*)d_in[5];
    const float* b1     = (const float*)d_in[6];
    const float* w2     = (const float*)d_in[7];
    const float* b2     = (const float*)d_in[8];
    const float* ascale = (const float*)d_in[9];
    const float* wi2t   = (const float*)d_in[10];
    const float* bi2t   = (const float*)d_in[11];
    const float* wt2i   = (const float*)d_in[12];
    const float* bt2i   = (const float*)d_in[13];
    const float* temp   = (const float*)d_in[14];
    float* out = (float*)d_out;

    cudaFuncSetAttribute(k_capW, cudaFuncAttributeMaxDynamicSharedMemorySize, LTC * CCH * 4);
    cudaFuncSetAttribute(k_pair, cudaFuncAttributeMaxDynamicSharedMemorySize, SMEM_FLOATS * 4);

    k_inv<<<BB * LVC, 128>>>(img);
    k_cap<<<NCAPC * LTC, 128>>>(cap);
    k_attnx<<<BB * NSP, 128>>>(img);
    k_capW<<<NCAPC * 2, 256, LTC * CCH * 4>>>(wi2t, bi2t, wt2i, bt2i);
    k_W0<<<BB * NSP, 128>>>(img, gamma, beta, w1, b1, w2, b2);
    k_attn_y<<<BB * NSP, 64>>>(img);
    k_pair<<<NCAPC * BB, 256, SMEM_FLOATS * 4>>>(img, ascale, temp, out);
}

// round 8
// speedup vs baseline: 1.0983x; 1.0981x over previous
#include <cuda_runtime.h>
#include <math.h>

#define BB 64
#define NCAPC 64
#define LVC 197
#define NSP 196
#define LTC 32
#define CCH 512
#define NKEEP 98
#define KEEPEDC 49
#define HIDC 102
#define LN_EPSF 1e-5f

typedef unsigned long long ull;

__device__ float g_inv_img[BB * LVC];
__device__ float g_attn_x[BB * NSP];
__device__ float g_attn_y[(size_t)NCAPC * BB * NSP];     // [i][r], r = b*196+j
__device__ float g_W0[(size_t)BB * NSP * KEEPEDC];
__device__ float g_CAT[(size_t)NCAPC * 96 * CCH];
__device__ float g_gloT[CCH * NCAPC];

__device__ __forceinline__ float warpReduceSum(float v) {
    #pragma unroll
    for (int o = 16; o > 0; o >>= 1) v += __shfl_xor_sync(0xffffffffu, v, o);
    return v;
}
__device__ __forceinline__ float warpReduceMax(float v) {
    #pragma unroll
    for (int o = 16; o > 0; o >>= 1) v = fmaxf(v, __shfl_xor_sync(0xffffffffu, v, o));
    return v;
}
__device__ __forceinline__ void fma2(ull& acc, ull a, ull b) {
    asm("fma.rn.f32x2 %0, %1, %2, %0;" : "+l"(acc) : "l"(a), "l"(b));
}
__device__ __forceinline__ ull pack2(float a, float b) {
    ull r; asm("mov.b64 %0, {%1, %2};" : "=l"(r) : "f"(a), "f"(b)); return r;
}
__device__ __forceinline__ float2 unpack2(ull v) {
    float2 f; asm("mov.b64 {%0, %1}, %2;" : "=f"(f.x), "=f"(f.y) : "l"(v)); return f;
}

// ---------------- K1: inverse norms ----------------
__global__ void k_inv(const float* __restrict__ img) {
    int r = blockIdx.x;
    const float* x = img + (size_t)r * CCH;
    int tid = threadIdx.x;
    float ss = 0.f;
    for (int c = tid; c < CCH; c += 128) { float v = x[c]; ss += v * v; }
    __shared__ float red[4];
    ss = warpReduceSum(ss);
    if ((tid & 31) == 0) red[tid >> 5] = ss;
    __syncthreads();
    if (tid == 0) g_inv_img[r] = 1.f / fmaxf(sqrtf(red[0]+red[1]+red[2]+red[3]), 1e-12f);
}

// ---------------- K2: attn_x ----------------
__global__ void k_attnx(const float* __restrict__ img) {
    int r = blockIdx.x; int b = r / NSP; int j = r - b * NSP;
    const float* x0 = img + (size_t)b * LVC * CCH;
    const float* xj = x0 + (size_t)(1 + j) * CCH;
    int tid = threadIdx.x;
    float d = 0.f;
    for (int c = tid; c < CCH; c += 128) d += x0[c] * xj[c];
    __shared__ float red[4];
    d = warpReduceSum(d);
    if ((tid & 31) == 0) red[tid >> 5] = d;
    __syncthreads();
    if (tid == 0) {
        float t = red[0]+red[1]+red[2]+red[3];
        g_attn_x[r] = t * g_inv_img[b * LVC] * g_inv_img[b * LVC + 1 + j];
    }
}

// ---------------- K3: cap_norm rows + gloT ----------------
__global__ void k_cap(const float* __restrict__ cap) {
    int r = blockIdx.x; int i = r / LTC; int t = r - i * LTC;
    const float* x = cap + (size_t)r * CCH;
    int tid = threadIdx.x;
    float ss = 0.f;
    for (int c = tid; c < CCH; c += 128) { float v = x[c]; ss += v * v; }
    __shared__ float red[4]; __shared__ float s_inv;
    ss = warpReduceSum(ss);
    if ((tid & 31) == 0) red[tid >> 5] = ss;
    __syncthreads();
    if (tid == 0) s_inv = 1.f / fmaxf(sqrtf(red[0]+red[1]+red[2]+red[3]), 1e-12f);
    __syncthreads();
    float inv = s_inv;
    float* dst = g_CAT + ((size_t)i * 96 + t) * CCH;
    for (int c = tid; c < CCH; c += 128) {
        float v = x[c] * inv;
        dst[c] = v;
        if (t == 0) g_gloT[c * NCAPC + i] = v;
    }
}

// ---------------- K4: CAT rows 32..95 = cap_norm @ W + b ----------------
// grid: i(64) * which(2) * half(2) = 256 blocks, 256 threads, 1 output col each
__global__ __launch_bounds__(256) void k_capW(
    const float* __restrict__ wi2t, const float* __restrict__ bi2t,
    const float* __restrict__ wt2i, const float* __restrict__ bt2i) {
    extern __shared__ float s_xT[];     // [ci][34], 512*34 floats
    int bx = blockIdx.x;
    int i = bx >> 2; int which = (bx >> 1) & 1; int halfid = bx & 1;
    int tid = threadIdx.x;
    int col = halfid * 256 + tid;
    const float* src = g_CAT + (size_t)i * 96 * CCH;   // rows 0..31
    for (int idx = tid; idx < LTC * CCH; idx += 256) {
        int t = idx >> 9; int c = idx & 511;
        s_xT[c * 34 + t] = src[idx];
    }
    __syncthreads();
    const float* W = which ? wt2i : wi2t;
    const float* bias = which ? bt2i : bi2t;
    ull acc[16];
    #pragma unroll
    for (int p = 0; p < 16; p++) acc[p] = 0ull;
    float w = W[col];
    for (int ci = 0; ci < CCH; ci++) {
        float wn = (ci < CCH - 1) ? W[(size_t)(ci + 1) * CCH + col] : 0.f;
        ull ww = pack2(w, w);
        const ull* xr = (const ull*)(s_xT + ci * 34);
        #pragma unroll
        for (int p = 0; p < 16; p++) fma2(acc[p], xr[p], ww);
        w = wn;
    }
    float bb = bias[col];
    float* dst = g_CAT + ((size_t)i * 96 + 32 + which * 32) * CCH;
    #pragma unroll
    for (int p = 0; p < 16; p++) {
        float2 f = unpack2(acc[p]);
        dst[(size_t)(2 * p) * CCH + col]     = f.x + bb;
        dst[(size_t)(2 * p + 1) * CCH + col] = f.y + bb;
    }
}

// ---------------- K5: W0, 16 tokens per block ----------------
__global__ __launch_bounds__(256) void k_W0(const float* __restrict__ img,
                     const float* __restrict__ gamma, const float* __restrict__ beta,
                     const float* __restrict__ w1, const float* __restrict__ b1,
                     const float* __restrict__ w2, const float* __restrict__ b2) {
    __shared__ float s_y[16 * CCH];
    __shared__ float s_h[16 * 104];
    int tid = threadIdx.x;
    int lane = tid & 31, wid = tid >> 5;
    int r0 = blockIdx.x * 16;
    // LN: warp wid handles rows wid and wid+8
    #pragma unroll
    for (int rr = wid; rr < 16; rr += 8) {
        int tok = r0 + rr;
        int b = tok / NSP; int j = tok - b * NSP;
        const float* x = img + ((size_t)b * LVC + 1 + j) * CCH;
        float s = 0.f, ss = 0.f;
        for (int c = lane; c < CCH; c += 32) { float v = x[c]; s += v; ss += v * v; }
        s = warpReduceSum(s); ss = warpReduceSum(ss);
        float mean = s * (1.f / CCH);
        float var = ss * (1.f / CCH) - mean * mean;
        float rstd = 1.f / sqrtf(var + LN_EPSF);
        for (int c = lane; c < CCH; c += 32)
            s_y[rr * CCH + c] = (x[c] - mean) * rstd * gamma[c] + beta[c];
    }
    __syncthreads();
    // h = gelu(y @ w1 + b1): 16*102 tasks
    for (int task = tid; task < 16 * HIDC; task += 256) {
        int row = task / HIDC; int col = task - row * HIDC;
        float acc = b1[col];
        const float* yr = s_y + row * CCH;
        #pragma unroll 8
        for (int c = 0; c < CCH; c++) acc += yr[c] * w1[(size_t)c * HIDC + col];
        s_h[row * 104 + col] = 0.5f * acc * (1.f + erff(acc * 0.70710678118654752f));
    }
    __syncthreads();
    // W0 = h @ w2 + b2: 16*49 tasks
    for (int task = tid; task < 16 * KEEPEDC; task += 256) {
        int row = task / KEEPEDC; int col = task - row * KEEPEDC;
        float acc = b2[col];
        const float* hr = s_h + row * 104;
        #pragma unroll 6
        for (int c = 0; c < HIDC; c++) acc += hr[c] * w2[c * KEEPEDC + col];
        g_W0[(size_t)(r0 + row) * KEEPEDC + col] = acc;
    }
}

// ---------------- K6: attn_y tiled GEMM: 64 tokens x 64 captions per block ----------------
__global__ __launch_bounds__(256) void k_attn_y(const float* __restrict__ img) {
    __shared__ float s_x[32 * 68];     // [cc][token]
    __shared__ float s_g[32 * 68];     // [cc][cap]
    __shared__ int   s_off[64];
    __shared__ float s_inv[64];
    int tid = threadIdx.x;
    int r0 = blockIdx.x * 64;
    if (tid < 64) {
        int tok = r0 + tid;
        int b = tok / NSP; int j = tok - b * NSP;
        s_off[tid] = (b * LVC + 1 + j) * CCH;
        s_inv[tid] = g_inv_img[b * LVC + 1 + j];
    }
    __syncthreads();
    int tx = tid & 15, ty = tid >> 4;
    int i0 = tx * 4, t0 = ty * 4;
    float acc[4][4];
    #pragma unroll
    for (int a = 0; a < 4; a++)
        #pragma unroll
        for (int c = 0; c < 4; c++) acc[a][c] = 0.f;
    for (int c0 = 0; c0 < CCH; c0 += 32) {
        // load x tile: token = tid>>2, 8 channels at (tid&3)*8
        {
            int tk = tid >> 2; int cc0 = (tid & 3) * 8;
            const float* p = img + s_off[tk] + c0 + cc0;
            float4 v0 = *(const float4*)p;
            float4 v1 = *(const float4*)(p + 4);
            s_x[(cc0 + 0) * 68 + tk] = v0.x; s_x[(cc0 + 1) * 68 + tk] = v0.y;
            s_x[(cc0 + 2) * 68 + tk] = v0.z; s_x[(cc0 + 3) * 68 + tk] = v0.w;
            s_x[(cc0 + 4) * 68 + tk] = v1.x; s_x[(cc0 + 5) * 68 + tk] = v1.y;
            s_x[(cc0 + 6) * 68 + tk] = v1.z; s_x[(cc0 + 7) * 68 + tk] = v1.w;
        }
        // load g tile: cc = tid>>3, 8 caps at (tid&7)*8
        {
            int cc = tid >> 3; int ii = (tid & 7) * 8;
            const float* p = g_gloT + (size_t)(c0 + cc) * NCAPC + ii;
            *(float4*)(s_g + cc * 68 + ii)     = *(const float4*)p;
            *(float4*)(s_g + cc * 68 + ii + 4) = *(const float4*)(p + 4);
        }
        __syncthreads();
        for (int cc = 0; cc < 32; cc++) {
            float4 gv = *(const float4*)(s_g + cc * 68 + i0);
            float4 xv = *(const float4*)(s_x + cc * 68 + t0);
            float xa[4] = {xv.x, xv.y, xv.z, xv.w};
            float gb[4] = {gv.x, gv.y, gv.z, gv.w};
            #pragma unroll
            for (int a = 0; a < 4; a++)
                #pragma unroll
                for (int c = 0; c < 4; c++) acc[a][c] += xa[a] * gb[c];
        }
        __syncthreads();
    }
    #pragma unroll
    for (int a = 0; a < 4; a++) {
        float inv = s_inv[t0 + a];
        #pragma unroll
        for (int c = 0; c < 4; c++)
            g_attn_y[(size_t)(i0 + c) * (BB * NSP) + r0 + t0 + a] = acc[a][c] * inv;
    }
}

// ---------------- K7: per-pair fused kernel ----------------
#define ST_ROW 520
#define OFF_ST 0
#define SZ_ST (51 * ST_ROW)
#define OFF_U SZ_ST
#define OFF_A2 OFF_U                         // [jj][98] duplicated pairs: 98*98=9604
#define OFF_WNON2 (OFF_U + 98 * 98)          // 196 (duplicated)
#define OFF_E OFF_U                          // 96*132 = 12672
#define OFF_G (OFF_U + 96 * 132)
#define OFF_CM (OFF_G + 96 * 51)
#define OFF_CZ (OFF_CM + 51)
#define OFF_RM (OFF_CZ + 51)
#define OFF_RZ (OFF_RM + 32)
#define SZ_U (96 * 132 + 96 * 51 + 51 + 51 + 32 + 32)
#define OFF_SCORE (OFF_U + SZ_U)
#define OFF_ORDER (OFF_SCORE + 196)
#define OFF_RED (OFF_ORDER + 196)
#define OFF_SCAL (OFF_RED + 8)
#define SMEM_FLOATS (OFF_SCAL + 4)

__global__ __launch_bounds__(256, 1) void k_pair(
    const float* __restrict__ img,
    const float* __restrict__ aggr_scale_p,
    const float* __restrict__ temp_p,
    float* __restrict__ out) {
    extern __shared__ float sm[];
    float* s_st    = sm + OFF_ST;
    float* s_A2    = sm + OFF_A2;
    float* s_wnon2 = sm + OFF_WNON2;
    float* s_E     = sm + OFF_E;
    float* s_G     = sm + OFF_G;
    float* s_cm    = sm + OFF_CM;
    float* s_cz    = sm + OFF_CZ;
    float* s_rm    = sm + OFF_RM;
    float* s_rz    = sm + OFF_RZ;
    float* s_score = sm + OFF_SCORE;
    int*   s_order = (int*)(sm + OFF_ORDER);
    float* s_red   = sm + OFF_RED;
    float* s_scal  = sm + OFF_SCAL;

    int pair = blockIdx.x;
    int i = pair & (NCAPC - 1);
    int b = pair >> 6;
    int tid = threadIdx.x;
    int lane = tid & 31, wid = tid >> 5;

    // ---- 1. scores ----
    {
        const float* ay = g_attn_y + (size_t)i * (BB * NSP) + b * NSP;
        const float* ax = g_attn_x + (size_t)b * NSP;
        for (int j = tid; j < NSP; j += 256) s_score[j] = ax[j] + ay[j];
    }
    __syncthreads();

    // ---- 2. stable rank ----
    if (tid < NSP) {
        float sj = s_score[tid];
        int rank = 0;
        for (int j2 = 0; j2 < NSP; j2++) {
            float s2 = s_score[j2];
            rank += (s2 > sj) || (s2 == sj && j2 < tid);
        }
        s_order[rank] = tid;
    }
    __syncthreads();

    // ---- 3a. softmax over nonkeep scores (duplicated store) ----
    {
        float m = -INFINITY;
        for (int jj = NKEEP + tid; jj < NSP; jj += 256) m = fmaxf(m, s_score[s_order[jj]]);
        m = warpReduceMax(m);
        if (lane == 0) s_red[wid] = m;
    }
    __syncthreads();
    if (tid == 0) {
        float mm = -INFINITY;
        for (int w = 0; w < 8; w++) mm = fmaxf(mm, s_red[w]);
        s_scal[0] = mm;
    }
    __syncthreads();
    {
        float mnon = s_scal[0];
        float z = 0.f;
        for (int jj = NKEEP + tid; jj < NSP; jj += 256) {
            float e = expf(s_score[s_order[jj]] - mnon);
            s_wnon2[2 * (jj - NKEEP)] = e; s_wnon2[2 * (jj - NKEEP) + 1] = e;
            z += e;
        }
        z = warpReduceSum(z);
        if (lane == 0) s_red[wid] = z;
    }
    __syncthreads();
    if (tid == 0) {
        float zz = 0.f;
        for (int w = 0; w < 8; w++) zz += s_red[w];
        s_scal[1] = 1.f / zz;
    }
    // ---- 3b. gather A transposed-duplicated: s_A2[jj*98 + 2k{,+1}] ----
    {
        float ascale = aggr_scale_p[0];
        for (int idx = tid; idx < NKEEP * KEEPEDC; idx += 256) {
            int jj = idx / KEEPEDC; int k = idx - jj * KEEPEDC;
            int j = s_order[jj];
            float v = g_W0[((size_t)b * NSP + j) * KEEPEDC + k] * ascale;
            s_A2[jj * 98 + 2 * k] = v; s_A2[jj * 98 + 2 * k + 1] = v;
        }
    }
    __syncthreads();
    // ---- 3c. per-k softmax over 98 keep entries ----
    for (int k = wid; k < KEEPEDC; k += 8) {
        float km = -INFINITY;
        for (int jj = lane; jj < NKEEP; jj += 32) km = fmaxf(km, s_A2[jj * 98 + 2 * k]);
        km = warpReduceMax(km);
        float kz = 0.f;
        for (int jj = lane; jj < NKEEP; jj += 32) {
            float e = expf(s_A2[jj * 98 + 2 * k] - km);
            s_A2[jj * 98 + 2 * k] = e; s_A2[jj * 98 + 2 * k + 1] = e;
            kz += e;
        }
        kz = warpReduceSum(kz);
        float inv = 1.f / kz;
        for (int jj = lane; jj < NKEEP; jj += 32) {
            s_A2[jj * 98 + 2 * k] *= inv; s_A2[jj * 98 + 2 * k + 1] *= inv;
        }
    }
    __syncthreads();

    // ---- 4. aggr + extra + cls -> unnormalized sel_tok (packed f32x2 FMA) ----
    {
        const float* spbase = img + ((size_t)b * LVC + 1) * CCH;
        ull acc[KEEPEDC];
        #pragma unroll
        for (int k = 0; k < KEEPEDC; k++) acc[k] = 0ull;
        ull x = ((const ull*)(spbase + (size_t)s_order[0] * CCH))[tid];
        for (int jj = 0; jj < NKEEP; jj++) {
            int jn = s_order[jj + 1];           // jj=97 -> s_order[98], valid
            ull xn = ((const ull*)(spbase + (size_t)jn * CCH))[tid];
            const ull* arow = (const ull*)(s_A2 + jj * 98);
            #pragma unroll
            for (int k = 0; k < KEEPEDC; k++) fma2(acc[k], arow[k], x);
            x = xn;
        }
        ull wacc = 0ull;
        for (int jj = NKEEP; jj < NSP; jj++) {
            int jn = s_order[jj + 1 < NSP ? jj + 1 : NSP - 1];
            ull xn = ((const ull*)(spbase + (size_t)jn * CCH))[tid];
            fma2(wacc, ((const ull*)s_wnon2)[jj - NKEEP], x);
            x = xn;
        }
        float invz = s_scal[1];
        float2 cls = ((const float2*)(img + (size_t)b * LVC * CCH))[tid];
        int c0 = tid * 2;
        s_st[0 * ST_ROW + c0] = cls.x; s_st[0 * ST_ROW + c0 + 1] = cls.y;
        #pragma unroll
        for (int k = 0; k < KEEPEDC; k++) {
            float2 f = unpack2(acc[k]);
            s_st[(1 + k) * ST_ROW + c0]     = f.x;
            s_st[(1 + k) * ST_ROW + c0 + 1] = f.y;
        }
        float2 w = unpack2(wacc);
        s_st[50 * ST_ROW + c0]     = w.x * invz;
        s_st[50 * ST_ROW + c0 + 1] = w.y * invz;
    }
    __syncthreads();

    // ---- 5. L2-normalize sel_tok rows ----
    for (int row = wid; row < 51; row += 8) {
        float ssq = 0.f;
        for (int c = lane; c < CCH; c += 32) { float v = s_st[row * ST_ROW + c]; ssq += v * v; }
        ssq = warpReduceSum(ssq);
        float inv = 1.f / fmaxf(sqrtf(ssq), 1e-12f);
        for (int c = lane; c < CCH; c += 32) s_st[row * ST_ROW + c] *= inv;
    }
    __syncthreads();

    // ---- 6. G = CAT_i @ sel_tok^T (96x51, packed f32x2) ----
    {
        const float* E = g_CAT + (size_t)i * 96 * CCH;
        ull acc2[8][3][2];
        #pragma unroll
        for (int a = 0; a < 8; a++)
            #pragma unroll
            for (int l = 0; l < 3; l++) { acc2[a][l][0] = 0ull; acc2[a][l][1] = 0ull; }
        int lgrp = tid % 17, tq = tid / 17;
        bool active = (tid < 204);
        int l0 = lgrp * 3, t0 = tq * 8;
        for (int ch = 0; ch < 4; ch++) {
            int c0 = ch * 128;
            for (int idx = tid * 4; idx < 96 * 128; idx += 1024) {
                int t = idx >> 7; int cc = idx & 127;
                *(float4*)(s_E + t * 132 + cc) = *(const float4*)(E + (size_t)t * CCH + c0 + cc);
            }
            __syncthreads();
            if (active) {
                for (int cc = 0; cc < 128; cc += 4) {
                    ulonglong2 st0 = *(const ulonglong2*)(s_st + (l0 + 0) * ST_ROW + c0 + cc);
                    ulonglong2 st1 = *(const ulonglong2*)(s_st + (l0 + 1) * ST_ROW + c0 + cc);
                    ulonglong2 st2 = *(const ulonglong2*)(s_st + (l0 + 2) * ST_ROW + c0 + cc);
                    #pragma unroll
                    for (int a = 0; a < 8; a++) {
                        ulonglong2 e = *(const ulonglong2*)(s_E + (t0 + a) * 132 + cc);
                        fma2(acc2[a][0][0], e.x, st0.x); fma2(acc2[a][0][1], e.y, st0.y);
                        fma2(acc2[a][1][0], e.x, st1.x); fma2(acc2[a][1][1], e.y, st1.y);
                        fma2(acc2[a][2][0], e.x, st2.x); fma2(acc2[a][2][1], e.y, st2.y);
                    }
                }
            }
            __syncthreads();
        }
        if (active) {
            #pragma unroll
            for (int a = 0; a < 8; a++)
                #pragma unroll
                for (int l = 0; l < 3; l++) {
                    float2 p0 = unpack2(acc2[a][l][0]);
                    float2 p1 = unpack2(acc2[a][l][1]);
                    s_G[(t0 + a) * 51 + l0 + l] = (p0.x + p0.y) + (p1.x + p1.y);
                }
        }
    }
    __syncthreads();

    // ---- 7. softmaxes + final reduction ----
    float invtemp = 1.f / temp_p[0];
    if (tid < 51) {
        int l = tid;
        float cm = -INFINITY;
        for (int t = 0; t < 32; t++) cm = fmaxf(cm, s_G[(32 + t) * 51 + l] * invtemp);
        float cz = 0.f;
        for (int t = 0; t < 32; t++) cz += expf(s_G[(32 + t) * 51 + l] * invtemp - cm);
        s_cm[l] = cm; s_cz[l] = cz;
    } else if (tid >= 64 && tid < 96) {
        int t = tid - 64;
        float rm = -INFINITY;
        for (int l = 0; l < 51; l++) rm = fmaxf(rm, s_G[(64 + t) * 51 + l] * invtemp);
        float rz = 0.f;
        for (int l = 0; l < 51; l++) rz += expf(s_G[(64 + t) * 51 + l] * invtemp - rm);
        s_rm[t] = rm; s_rz[t] = rz;
    }
    __syncthreads();
    float part = 0.f;
    for (int idx = tid; idx < 32 * 51; idx += 256) {
        int t = idx / 51; int l = idx - t * 51;
        float g = s_G[t * 51 + l];
        float c2i = (g >= 0.f) ? g : 0.1f * g;
        float li = s_G[(32 + t) * 51 + l] * invtemp;
        float lt = s_G[(64 + t) * 51 + l] * invtemp;
        float ai = expf(li - s_cm[l]) / s_cz[l];
        float at = expf(lt - s_rm[t]) / s_rz[t];
        part += c2i * (ai * (1.f / 51.f) + at * (1.f / 32.f));
    }
    part = warpReduceSum(part);
    if (lane == 0) s_red[wid] = part;
    __syncthreads();
    if (tid == 0) {
        float s = 0.f;
        for (int w = 0; w < 8; w++) s += s_red[w];
        out[b * NCAPC + i] = s;
    }
}

// ---------------- launch ----------------
extern "C" void kernel_launch(void* const* d_in, const int* in_sizes, int n_in,
                              void* d_out, int out_size) {
    const float* img    = (const float*)d_in[0];
    const float* cap    = (const float*)d_in[1];
    const float* gamma  = (const float*)d_in[3];
    const float* beta   = (const float*)d_in[4];
    const float* w1     = (const float*)d_in[5];
    const float* b1     = (const float*)d_in[6];
    const float* w2     = (const float*)d_in[7];
    const float* b2     = (const float*)d_in[8];
    const float* ascale = (const float*)d_in[9];
    const float* wi2t   = (const float*)d_in[10];
    const float* bi2t   = (const float*)d_in[11];
    const float* wt2i   = (const float*)d_in[12];
    const float* bt2i   = (const float*)d_in[13];
    const float* temp   = (const float*)d_in[14];
    float* out = (float*)d_out;

    cudaFuncSetAttribute(k_capW, cudaFuncAttributeMaxDynamicSharedMemorySize, 512 * 34 * 4);
    cudaFuncSetAttribute(k_pair, cudaFuncAttributeMaxDynamicSharedMemorySize, SMEM_FLOATS * 4);

    k_inv<<<BB * LVC, 128>>>(img);
    k_cap<<<NCAPC * LTC, 128>>>(cap);
    k_attnx<<<BB * NSP, 128>>>(img);
    k_capW<<<NCAPC * 4, 256, 512 * 34 * 4>>>(wi2t, bi2t, wt2i, bt2i);
    k_W0<<<(BB * NSP) / 16, 256>>>(img, gamma, beta, w1, b1, w2, b2);
    k_attn_y<<<(BB * NSP) / 64, 256>>>(img);
    k_pair<<<NCAPC * BB, 256, SMEM_FLOATS * 4>>>(img, ascale, temp, out);
}